// round 1
// baseline (speedup 1.0000x reference)
#include <cuda_runtime.h>
#include <cstdint>

// ---------------- problem constants ----------------
#define B_      32
#define C_      256
#define HW_     56
#define PW      7
#define PP      49          // 7*7
#define NW      64          // windows per image (8*8)
#define BNW     (B_*NW)     // 2048
#define MTOK    (BNW*PP)    // 100352 tokens
#define HEADS_  8
#define DH_     32
#define INNER_  256
#define QS      (BNW*HEADS_*PP*DH_)   // 25,690,112 per q/k/v
#define OUT_ELEMS (B_*C_*HW_*HW_)     // 25,690,112

#define NEG_INF __int_as_float(0xff800000)

// ---------------- scratch (static device arrays; no allocation) ----------------
__device__ float g_xw[(size_t)MTOK * C_];       // gathered windows, token-major [M,256]
__device__ float g_qkv[(size_t)3 * QS];         // q,k,v each [bn][head][t][dh]
__device__ float g_oattn[(size_t)MTOK * INNER_];// attn@v, token-major [M,256]
__device__ float g_otok[(size_t)MTOK * C_];     // out proj result, token-major
__device__ float g_mask[NW * PP * PP];          // bias + shift masks

// ---------------- kernel 1: gather + roll(-3) + window permute ----------------
// block: (xsrow 0..55, ctile 0..7, b 0..31); reads x coalesced along w,
// writes g_xw coalesced along c via smem transpose.
__global__ void gather_kernel(const float* __restrict__ x) {
    __shared__ float s[32 * 57];
    int xsrow = blockIdx.x;
    int c0 = blockIdx.y * 32;
    int b = blockIdx.z;
    int r = xsrow + 3; if (r >= 56) r -= 56;
    const float* xb = x + ((size_t)(b * 256 + c0) * 3136) + r * 56;
    for (int i = threadIdx.x; i < 32 * 56; i += blockDim.x) {
        int c = i / 56, col = i - c * 56;
        s[c * 57 + col] = xb[(size_t)c * 3136 + col];
    }
    __syncthreads();
    int wi = xsrow / 7, pi = xsrow - wi * 7;
    for (int j = threadIdx.x; j < 32 * 56; j += blockDim.x) {
        int cw = j & 31, pos = j >> 5;
        int wj = pos / 7, pj = pos - wj * 7;
        int col = pos + 3; if (col >= 56) col -= 56;
        int token = (b * 64 + wi * 8 + wj) * 49 + pi * 7 + pj;
        g_xw[(size_t)token * 256 + c0 + cw] = s[cw * 57 + col];
    }
}

// ---------------- kernel 2: mask = rel-pos bias + shift masks ----------------
__global__ void mask_kernel(const float* __restrict__ pe) {
    int n = blockIdx.x;   // 0..63
    for (int e = threadIdx.x; e < 2401; e += blockDim.x) {
        int i = e / 49, j = e - i * 49;
        int i7 = i % 7, j7 = j % 7;
        int r0 = j / 7 - i / 7 + 6;
        int r1 = j7 - i7 + 6;
        float v = pe[r0 * 13 + r1];
        if (n >= 56 && ((i >= 28) != (j >= 28))) v = NEG_INF;
        if ((n == 55 || n == 63) && ((i7 >= 4) != (j7 >= 4))) v = NEG_INF;
        g_mask[n * 2401 + e] = v;
    }
}

// ---------------- kernel 3: QKV GEMM ----------------
// C[100352,768] = g_xw[100352,256] @ wqkv[256,768]; scatter into q/k/v layout.
// BM=128, BN=64, BK=16, 256 threads, 8x4 micro-tile.
__global__ __launch_bounds__(256) void gemm_qkv(const float* __restrict__ wqkv) {
    __shared__ __align__(16) float As[16 * 132];
    __shared__ __align__(16) float Bs[16 * 64];
    int m0 = blockIdx.x * 128;
    int n0 = blockIdx.y * 64;
    int tid = threadIdx.x;
    int tx = tid & 15, ty = tid >> 4;
    float acc[8][4];
#pragma unroll
    for (int r = 0; r < 8; r++)
#pragma unroll
        for (int c = 0; c < 4; c++) acc[r][c] = 0.f;

    for (int k0 = 0; k0 < 256; k0 += 16) {
#pragma unroll
        for (int it = 0; it < 2; it++) {
            int idx = tid + it * 256;
            int row = idx >> 2, c4 = idx & 3;
            float4 a = *(const float4*)(&g_xw[(size_t)(m0 + row) * 256 + k0 + c4 * 4]);
            As[(c4 * 4 + 0) * 132 + row] = a.x;
            As[(c4 * 4 + 1) * 132 + row] = a.y;
            As[(c4 * 4 + 2) * 132 + row] = a.z;
            As[(c4 * 4 + 3) * 132 + row] = a.w;
        }
        {
            int kk = tid >> 4, nn = (tid & 15) * 4;
            *(float4*)&Bs[kk * 64 + nn] =
                *(const float4*)(&wqkv[(size_t)(k0 + kk) * 768 + n0 + nn]);
        }
        __syncthreads();
#pragma unroll
        for (int kk = 0; kk < 16; kk++) {
            float4 a0 = *(const float4*)&As[kk * 132 + ty * 8];
            float4 a1 = *(const float4*)&As[kk * 132 + ty * 8 + 4];
            float4 b  = *(const float4*)&Bs[kk * 64 + tx * 4];
            float ar[8] = {a0.x, a0.y, a0.z, a0.w, a1.x, a1.y, a1.z, a1.w};
            float br[4] = {b.x, b.y, b.z, b.w};
#pragma unroll
            for (int r = 0; r < 8; r++)
#pragma unroll
                for (int c = 0; c < 4; c++) acc[r][c] = fmaf(ar[r], br[c], acc[r][c]);
        }
        __syncthreads();
    }

    int mat = n0 >> 8;   // 0=q,1=k,2=v (BN=64 tile never straddles a 256 boundary)
    float* dst = g_qkv + (size_t)mat * QS;
#pragma unroll
    for (int rr = 0; rr < 8; rr++) {
        int m = m0 + ty * 8 + rr;
        int bn = m / 49, t = m - bn * 49;
#pragma unroll
        for (int cc = 0; cc < 4; cc++) {
            int n = (n0 + tx * 4 + cc) & 255;
            int head = n >> 5, dh = n & 31;
            dst[(size_t)((bn * 8 + head) * 49 + t) * 32 + dh] = acc[rr][cc];
        }
    }
}

// ---------------- kernel 4: attention per (bn, head) ----------------
__global__ __launch_bounds__(128) void attn_kernel(float* __restrict__ dout) {
    __shared__ __align__(16) float qs[49 * 36];
    __shared__ __align__(16) float ks[49 * 36];
    __shared__ __align__(16) float vs[49 * 36];
    __shared__ float Ss[49 * 50];
    int bn = blockIdx.x >> 3;
    int h = blockIdx.x & 7;
    int n = bn & 63;
    int tid = threadIdx.x;

    const float* qg = g_qkv + (size_t)((bn * 8 + h) * 49) * 32;
    const float* kg = qg + (size_t)QS;
    const float* vg = qg + (size_t)2 * QS;
    for (int i = tid; i < 1568; i += 128) {
        int t = i >> 5, d = i & 31;
        qs[t * 36 + d] = qg[i];
        ks[t * 36 + d] = kg[i];
        vs[t * 36 + d] = vg[i];
    }
    __syncthreads();

    const float scale = 0.17677669529663687f;   // 1/sqrt(32)
    const float* mk = g_mask + n * 2401;
    for (int o = tid; o < 2401; o += 128) {
        int i = o / 49, j = o - i * 49;
        const float4* qv = (const float4*)(qs + i * 36);
        const float4* kv = (const float4*)(ks + j * 36);
        float a = 0.f;
#pragma unroll
        for (int u = 0; u < 8; u++) {
            float4 x = qv[u], y = kv[u];
            a = fmaf(x.x, y.x, a); a = fmaf(x.y, y.y, a);
            a = fmaf(x.z, y.z, a); a = fmaf(x.w, y.w, a);
        }
        Ss[i * 50 + j] = a * scale + mk[o];
    }
    __syncthreads();

    if (tid < 49) {
        float m = NEG_INF;
        for (int j = 0; j < 49; j++) m = fmaxf(m, Ss[tid * 50 + j]);
        float sum = 0.f;
        for (int j = 0; j < 49; j++) {
            float e = __expf(Ss[tid * 50 + j] - m);
            Ss[tid * 50 + j] = e;
            sum += e;
        }
        float inv = 1.f / sum;
        for (int j = 0; j < 49; j++) Ss[tid * 50 + j] *= inv;
    }
    __syncthreads();

    // attn output (coalesced)
    float* ao = dout + (size_t)OUT_ELEMS + (size_t)((bn * 8 + h) * 49) * 49;
    for (int o = tid; o < 2401; o += 128) {
        int i = o / 49, j = o - i * 49;
        ao[o] = Ss[i * 50 + j];
    }

    // O = attn @ v  (float4 over dh)
    const float4* vv = (const float4*)vs;   // rows of 9 float4 (36 floats)
    for (int o = tid; o < 49 * 8; o += 128) {
        int i = o >> 3, d4 = o & 7;
        float4 a = make_float4(0.f, 0.f, 0.f, 0.f);
        for (int j = 0; j < 49; j++) {
            float sij = Ss[i * 50 + j];
            float4 v4 = vv[j * 9 + d4];
            a.x = fmaf(sij, v4.x, a.x);
            a.y = fmaf(sij, v4.y, a.y);
            a.z = fmaf(sij, v4.z, a.z);
            a.w = fmaf(sij, v4.w, a.w);
        }
        *(float4*)&g_oattn[(size_t)(bn * 49 + i) * 256 + h * 32 + d4 * 4] = a;
    }
}

// ---------------- kernel 5: output GEMM + bias ----------------
__global__ __launch_bounds__(256) void gemm_out(const float* __restrict__ wout,
                                                const float* __restrict__ bout) {
    __shared__ __align__(16) float As[16 * 132];
    __shared__ __align__(16) float Bs[16 * 64];
    int m0 = blockIdx.x * 128;
    int n0 = blockIdx.y * 64;
    int tid = threadIdx.x;
    int tx = tid & 15, ty = tid >> 4;
    float acc[8][4];
#pragma unroll
    for (int r = 0; r < 8; r++)
#pragma unroll
        for (int c = 0; c < 4; c++) acc[r][c] = 0.f;

    for (int k0 = 0; k0 < 256; k0 += 16) {
#pragma unroll
        for (int it = 0; it < 2; it++) {
            int idx = tid + it * 256;
            int row = idx >> 2, c4 = idx & 3;
            float4 a = *(const float4*)(&g_oattn[(size_t)(m0 + row) * 256 + k0 + c4 * 4]);
            As[(c4 * 4 + 0) * 132 + row] = a.x;
            As[(c4 * 4 + 1) * 132 + row] = a.y;
            As[(c4 * 4 + 2) * 132 + row] = a.z;
            As[(c4 * 4 + 3) * 132 + row] = a.w;
        }
        {
            int kk = tid >> 4, nn = (tid & 15) * 4;
            *(float4*)&Bs[kk * 64 + nn] =
                *(const float4*)(&wout[(size_t)(k0 + kk) * 256 + n0 + nn]);
        }
        __syncthreads();
#pragma unroll
        for (int kk = 0; kk < 16; kk++) {
            float4 a0 = *(const float4*)&As[kk * 132 + ty * 8];
            float4 a1 = *(const float4*)&As[kk * 132 + ty * 8 + 4];
            float4 b  = *(const float4*)&Bs[kk * 64 + tx * 4];
            float ar[8] = {a0.x, a0.y, a0.z, a0.w, a1.x, a1.y, a1.z, a1.w};
            float br[4] = {b.x, b.y, b.z, b.w};
#pragma unroll
            for (int r = 0; r < 8; r++)
#pragma unroll
                for (int c = 0; c < 4; c++) acc[r][c] = fmaf(ar[r], br[c], acc[r][c]);
        }
        __syncthreads();
    }

    float4 bv = *(const float4*)&bout[n0 + tx * 4];
#pragma unroll
    for (int rr = 0; rr < 8; rr++) {
        int m = m0 + ty * 8 + rr;
        float4 o = make_float4(acc[rr][0] + bv.x, acc[rr][1] + bv.y,
                               acc[rr][2] + bv.z, acc[rr][3] + bv.w);
        *(float4*)&g_otok[(size_t)m * 256 + n0 + tx * 4] = o;
    }
}

// ---------------- kernel 6: scatter (inverse window permute + roll(+3)) ----------------
__global__ void scatter_kernel(float* __restrict__ out) {
    __shared__ float s[32 * 57];
    int xsrow = blockIdx.x;
    int c0 = blockIdx.y * 32;
    int b = blockIdx.z;
    int wi = xsrow / 7, pi = xsrow - wi * 7;
    for (int j = threadIdx.x; j < 32 * 56; j += blockDim.x) {
        int cw = j & 31, pos = j >> 5;
        int wj = pos / 7, pj = pos - wj * 7;
        int col = pos + 3; if (col >= 56) col -= 56;
        int token = (b * 64 + wi * 8 + wj) * 49 + pi * 7 + pj;
        s[cw * 57 + col] = g_otok[(size_t)token * 256 + c0 + cw];
    }
    __syncthreads();
    int r = xsrow + 3; if (r >= 56) r -= 56;
    float* ob = out + ((size_t)(b * 256 + c0) * 3136) + r * 56;
    for (int i = threadIdx.x; i < 32 * 56; i += blockDim.x) {
        int c = i / 56, col = i - c * 56;
        ob[(size_t)c * 3136 + col] = s[c * 57 + col];
    }
}

// ---------------- launch ----------------
extern "C" void kernel_launch(void* const* d_in, const int* in_sizes, int n_in,
                              void* d_out, int out_size) {
    const float* x    = (const float*)d_in[0];
    const float* pe   = (const float*)d_in[1];
    const float* wqkv = (const float*)d_in[2];
    const float* wout = (const float*)d_in[3];
    const float* bout = (const float*)d_in[4];
    float* out = (float*)d_out;

    gather_kernel<<<dim3(56, 8, 32), 256>>>(x);
    mask_kernel<<<64, 256>>>(pe);
    gemm_qkv<<<dim3(MTOK / 128, 768 / 64), 256>>>(wqkv);
    attn_kernel<<<BNW * HEADS_, 128>>>(out);
    gemm_out<<<dim3(MTOK / 128, 256 / 64), 256>>>(wout, bout);
    scatter_kernel<<<dim3(56, 8, 32), 256>>>(out);
}

// round 3
// speedup vs baseline: 1.8109x; 1.8109x over previous
#include <cuda_runtime.h>
#include <cstdint>

// ---------------- problem constants ----------------
#define B_      32
#define PP      49
#define NW      64
#define BNW     2048
#define MTOK    100352                 // BNW*49
#define QS      25690112               // BNW*8*49*32
#define OUT_ELEMS 25690112

#define NEG_INF __int_as_float(0xff800000)

// ---------------- scratch ----------------
__device__ float g_xw[(size_t)MTOK * 256];
__device__ float g_qkv[(size_t)3 * QS];
__device__ float g_oattn[(size_t)MTOK * 256];
__device__ float g_otok[(size_t)MTOK * 256];
__device__ float g_mask[NW * PP * PP];

// ---------------- tf32 helpers ----------------
__device__ __forceinline__ unsigned f2tf(float f) {
    unsigned u; asm("cvt.rna.tf32.f32 %0, %1;" : "=r"(u) : "f"(f)); return u;
}
// D += A(16x8) * B(8x8), tf32 in, f32 accum.
// frag map: g=lane>>2, t=lane&3
//   a0=A[g][t]  a1=A[g+8][t]  a2=A[g][t+4]  a3=A[g+8][t+4]
//   b0=B[t][g]  b1=B[t+4][g]
//   c0=C[g][2t] c1=C[g][2t+1] c2=C[g+8][2t] c3=C[g+8][2t+1]
__device__ __forceinline__ void mma_tf32(float* c, const unsigned* a, const unsigned* b) {
    asm volatile("mma.sync.aligned.m16n8k8.row.col.f32.tf32.tf32.f32 "
        "{%0,%1,%2,%3}, {%4,%5,%6,%7}, {%8,%9}, {%0,%1,%2,%3};"
        : "+f"(c[0]), "+f"(c[1]), "+f"(c[2]), "+f"(c[3])
        : "r"(a[0]), "r"(a[1]), "r"(a[2]), "r"(a[3]), "r"(b[0]), "r"(b[1]));
}

// ---------------- kernel 1: gather + roll(-3) + window permute ----------------
__global__ void gather_kernel(const float* __restrict__ x) {
    __shared__ float s[32 * 57];
    int xsrow = blockIdx.x;
    int c0 = blockIdx.y * 32;
    int b = blockIdx.z;
    int r = xsrow + 3; if (r >= 56) r -= 56;
    const float* xb = x + ((size_t)(b * 256 + c0) * 3136) + r * 56;
    for (int i = threadIdx.x; i < 32 * 56; i += blockDim.x) {
        int c = i / 56, col = i - c * 56;
        s[c * 57 + col] = xb[(size_t)c * 3136 + col];
    }
    __syncthreads();
    int wi = xsrow / 7, pi = xsrow - wi * 7;
    for (int j = threadIdx.x; j < 32 * 56; j += blockDim.x) {
        int cw = j & 31, pos = j >> 5;
        int wj = pos / 7, pj = pos - wj * 7;
        int col = pos + 3; if (col >= 56) col -= 56;
        int token = (b * 64 + wi * 8 + wj) * 49 + pi * 7 + pj;
        g_xw[(size_t)token * 256 + c0 + cw] = s[cw * 57 + col];
    }
}

// ---------------- kernel 2: mask ----------------
__global__ void mask_kernel(const float* __restrict__ pe) {
    int n = blockIdx.x;
    for (int e = threadIdx.x; e < 2401; e += blockDim.x) {
        int i = e / 49, j = e - i * 49;
        int i7 = i % 7, j7 = j % 7;
        int r0 = j / 7 - i / 7 + 6;
        int r1 = j7 - i7 + 6;
        float v = pe[r0 * 13 + r1];
        if (n >= 56 && ((i >= 28) != (j >= 28))) v = NEG_INF;
        if ((n == 55 || n == 63) && ((i7 >= 4) != (j7 >= 4))) v = NEG_INF;
        g_mask[n * 2401 + e] = v;
    }
}

// ---------------- kernel 3: QKV GEMM (tf32 tensor cores) ----------------
// C[100352,768] = g_xw @ wqkv. BM=128 BN=64 BK=16, 8 warps (4m x 2n), warp 32x32.
__global__ __launch_bounds__(256) void gemm_qkv_tc(const float* __restrict__ wqkv) {
    __shared__ unsigned As[128 * 20];
    __shared__ unsigned Bs[64 * 20];
    int m0 = blockIdx.y * 128;
    int n0 = blockIdx.x * 64;
    int tid = threadIdx.x;
    int lane = tid & 31, wid = tid >> 5;
    int g = lane >> 2, t = lane & 3;
    int wm = (wid & 3) * 32, wn = (wid >> 2) * 32;

    float acc[2][4][4];
#pragma unroll
    for (int mf = 0; mf < 2; mf++)
#pragma unroll
        for (int nf = 0; nf < 4; nf++)
#pragma unroll
            for (int v = 0; v < 4; v++) acc[mf][nf][v] = 0.f;

    int arow = tid >> 2, ac4 = (tid & 3) * 4;
    int bkk = tid >> 4, bnn = (tid & 15) * 4;
    const float* Ab = g_xw + (size_t)m0 * 256;

    float4 ra0 = *(const float4*)(Ab + (size_t)arow * 256 + ac4);
    float4 ra1 = *(const float4*)(Ab + (size_t)(arow + 64) * 256 + ac4);
    float4 rb  = *(const float4*)(wqkv + (size_t)bkk * 768 + n0 + bnn);

    for (int kt = 0; kt < 16; kt++) {
        unsigned* ap = &As[arow * 20 + ac4];
        ap[0] = f2tf(ra0.x); ap[1] = f2tf(ra0.y); ap[2] = f2tf(ra0.z); ap[3] = f2tf(ra0.w);
        ap = &As[(arow + 64) * 20 + ac4];
        ap[0] = f2tf(ra1.x); ap[1] = f2tf(ra1.y); ap[2] = f2tf(ra1.z); ap[3] = f2tf(ra1.w);
        Bs[(bnn + 0) * 20 + bkk] = f2tf(rb.x);
        Bs[(bnn + 1) * 20 + bkk] = f2tf(rb.y);
        Bs[(bnn + 2) * 20 + bkk] = f2tf(rb.z);
        Bs[(bnn + 3) * 20 + bkk] = f2tf(rb.w);
        __syncthreads();
        if (kt < 15) {
            int k0 = (kt + 1) * 16;
            ra0 = *(const float4*)(Ab + (size_t)arow * 256 + k0 + ac4);
            ra1 = *(const float4*)(Ab + (size_t)(arow + 64) * 256 + k0 + ac4);
            rb  = *(const float4*)(wqkv + (size_t)(k0 + bkk) * 768 + n0 + bnn);
        }
#pragma unroll
        for (int kf = 0; kf < 2; kf++) {
            unsigned a[2][4], b[4][2];
#pragma unroll
            for (int mf = 0; mf < 2; mf++) {
                int base = (wm + mf * 16 + g) * 20 + kf * 8 + t;
                a[mf][0] = As[base];
                a[mf][1] = As[base + 8 * 20];
                a[mf][2] = As[base + 4];
                a[mf][3] = As[base + 8 * 20 + 4];
            }
#pragma unroll
            for (int nf = 0; nf < 4; nf++) {
                int bb = (wn + nf * 8 + g) * 20 + kf * 8 + t;
                b[nf][0] = Bs[bb];
                b[nf][1] = Bs[bb + 4];
            }
#pragma unroll
            for (int mf = 0; mf < 2; mf++)
#pragma unroll
                for (int nf = 0; nf < 4; nf++)
                    mma_tf32(acc[mf][nf], a[mf], b[nf]);
        }
        __syncthreads();
    }

#pragma unroll
    for (int mf = 0; mf < 2; mf++) {
        int row0 = m0 + wm + mf * 16 + g;
        int bn0 = row0 / 49, tk0 = row0 - bn0 * 49;
        int row1 = row0 + 8;
        int bn1 = row1 / 49, tk1 = row1 - bn1 * 49;
#pragma unroll
        for (int nf = 0; nf < 4; nf++) {
            int ncol = n0 + wn + nf * 8 + 2 * t;
            int mat = ncol >> 8, wcol = ncol & 255;
            int head = wcol >> 5, dh = wcol & 31;
            float* dst = g_qkv + (size_t)mat * QS;
            *(float2*)&dst[(size_t)((bn0 * 8 + head) * 49 + tk0) * 32 + dh] =
                make_float2(acc[mf][nf][0], acc[mf][nf][1]);
            *(float2*)&dst[(size_t)((bn1 * 8 + head) * 49 + tk1) * 32 + dh] =
                make_float2(acc[mf][nf][2], acc[mf][nf][3]);
        }
    }
}

// ---------------- kernel 4: attention (tf32 MMA) ----------------
// one block per (bn,head); 4 warps. S padded 64x56, O padded 64x32.
__global__ __launch_bounds__(128) void attn_tc(float* __restrict__ dout) {
    __shared__ unsigned SBuf[4320];        // Qs[64*36] | Ks[56*36]; Ps[64*60] aliases
    __shared__ unsigned Vt[32 * 60];
    unsigned* Qs = SBuf;
    unsigned* Ks = SBuf + 64 * 36;
    unsigned* Ps = SBuf;

    int bn = blockIdx.x >> 3, h = blockIdx.x & 7, n = bn & 63;
    int tid = threadIdx.x, lane = tid & 31, w = tid >> 5;
    int g = lane >> 2, t = lane & 3;

    const float* qg = g_qkv + (size_t)((bn * 8 + h) * 49) * 32;
    const float* kg = qg + (size_t)QS;
    const float* vg = qg + (size_t)2 * QS;

    // zero pads: Qs rows 49..63 (540), Ks rows 49..55 (252), all Vt (1920)
    for (int i = tid; i < 2712; i += 128) {
        if (i < 540) Qs[49 * 36 + i] = 0;
        else if (i < 792) Ks[49 * 36 + (i - 540)] = 0;
        else Vt[i - 792] = 0;
    }
    __syncthreads();
    for (int i4 = tid; i4 < 392; i4 += 128) {
        int tk = i4 >> 3, d4 = (i4 & 7) * 4;
        float4 q = *(const float4*)(qg + tk * 32 + d4);
        float4 k = *(const float4*)(kg + tk * 32 + d4);
        float4 v = *(const float4*)(vg + tk * 32 + d4);
        unsigned* qp = &Qs[tk * 36 + d4];
        qp[0] = f2tf(q.x); qp[1] = f2tf(q.y); qp[2] = f2tf(q.z); qp[3] = f2tf(q.w);
        unsigned* kp = &Ks[tk * 36 + d4];
        kp[0] = f2tf(k.x); kp[1] = f2tf(k.y); kp[2] = f2tf(k.z); kp[3] = f2tf(k.w);
        Vt[(d4 + 0) * 60 + tk] = f2tf(v.x);
        Vt[(d4 + 1) * 60 + tk] = f2tf(v.y);
        Vt[(d4 + 2) * 60 + tk] = f2tf(v.z);
        Vt[(d4 + 3) * 60 + tk] = f2tf(v.w);
    }
    __syncthreads();

    // S = Q @ K^T  (warp w: rows 16w..16w+15; 7 n-frags cover cols 0..55)
    float s[7][4];
#pragma unroll
    for (int nf = 0; nf < 7; nf++)
#pragma unroll
        for (int v = 0; v < 4; v++) s[nf][v] = 0.f;
#pragma unroll
    for (int kf = 0; kf < 4; kf++) {
        unsigned a[4];
        int base = (w * 16 + g) * 36 + kf * 8 + t;
        a[0] = Qs[base]; a[1] = Qs[base + 8 * 36];
        a[2] = Qs[base + 4]; a[3] = Qs[base + 8 * 36 + 4];
#pragma unroll
        for (int nf = 0; nf < 7; nf++) {
            unsigned b[2];
            int bb = (nf * 8 + g) * 36 + kf * 8 + t;
            b[0] = Ks[bb]; b[1] = Ks[bb + 4];
            mma_tf32(s[nf], a, b);
        }
    }

    // scale + mask
    const float scale = 0.17677669529663687f;
    const float* mk = g_mask + n * 2401;
    int row0 = w * 16 + g, row1 = row0 + 8;
#pragma unroll
    for (int nf = 0; nf < 7; nf++) {
        int c0 = nf * 8 + 2 * t, c1 = c0 + 1;
        float m00 = (c0 < 49) ? ((row0 < 49) ? __ldg(mk + row0 * 49 + c0) : 0.f) : NEG_INF;
        float m01 = (c1 < 49) ? ((row0 < 49) ? __ldg(mk + row0 * 49 + c1) : 0.f) : NEG_INF;
        float m10 = (c0 < 49) ? ((row1 < 49) ? __ldg(mk + row1 * 49 + c0) : 0.f) : NEG_INF;
        float m11 = (c1 < 49) ? ((row1 < 49) ? __ldg(mk + row1 * 49 + c1) : 0.f) : NEG_INF;
        s[nf][0] = s[nf][0] * scale + m00;
        s[nf][1] = s[nf][1] * scale + m01;
        s[nf][2] = s[nf][2] * scale + m10;
        s[nf][3] = s[nf][3] * scale + m11;
    }

    // softmax over rows (row split across 4 lanes of the same group)
    float mx0 = NEG_INF, mx1 = NEG_INF;
#pragma unroll
    for (int nf = 0; nf < 7; nf++) {
        mx0 = fmaxf(mx0, fmaxf(s[nf][0], s[nf][1]));
        mx1 = fmaxf(mx1, fmaxf(s[nf][2], s[nf][3]));
    }
    mx0 = fmaxf(mx0, __shfl_xor_sync(0xffffffffu, mx0, 1));
    mx0 = fmaxf(mx0, __shfl_xor_sync(0xffffffffu, mx0, 2));
    mx1 = fmaxf(mx1, __shfl_xor_sync(0xffffffffu, mx1, 1));
    mx1 = fmaxf(mx1, __shfl_xor_sync(0xffffffffu, mx1, 2));
    float sm0 = 0.f, sm1 = 0.f;
#pragma unroll
    for (int nf = 0; nf < 7; nf++) {
        s[nf][0] = __expf(s[nf][0] - mx0);
        s[nf][1] = __expf(s[nf][1] - mx0);
        s[nf][2] = __expf(s[nf][2] - mx1);
        s[nf][3] = __expf(s[nf][3] - mx1);
        sm0 += s[nf][0] + s[nf][1];
        sm1 += s[nf][2] + s[nf][3];
    }
    sm0 += __shfl_xor_sync(0xffffffffu, sm0, 1);
    sm0 += __shfl_xor_sync(0xffffffffu, sm0, 2);
    sm1 += __shfl_xor_sync(0xffffffffu, sm1, 1);
    sm1 += __shfl_xor_sync(0xffffffffu, sm1, 2);
    float inv0 = 1.f / sm0, inv1 = 1.f / sm1;
#pragma unroll
    for (int nf = 0; nf < 7; nf++) {
        s[nf][0] *= inv0; s[nf][1] *= inv0;
        s[nf][2] *= inv1; s[nf][3] *= inv1;
    }

    __syncthreads();   // everyone done reading Qs/Ks before Ps overwrites SBuf

    // write attn output + Ps
    float* ao = dout + (size_t)OUT_ELEMS + (size_t)((bn * 8 + h) * 49) * 49;
#pragma unroll
    for (int nf = 0; nf < 7; nf++) {
        int c0 = nf * 8 + 2 * t;
        if (row0 < 49) {
            if (c0 < 49) ao[row0 * 49 + c0] = s[nf][0];
            if (c0 + 1 < 49) ao[row0 * 49 + c0 + 1] = s[nf][1];
        }
        if (row1 < 49) {
            if (c0 < 49) ao[row1 * 49 + c0] = s[nf][2];
            if (c0 + 1 < 49) ao[row1 * 49 + c0 + 1] = s[nf][3];
        }
        uint2 p0 = make_uint2(f2tf(s[nf][0]), f2tf(s[nf][1]));
        uint2 p1 = make_uint2(f2tf(s[nf][2]), f2tf(s[nf][3]));
        *(uint2*)&Ps[row0 * 60 + c0] = p0;
        *(uint2*)&Ps[row1 * 60 + c0] = p1;
    }
    __syncthreads();

    // O = P @ V
    float o[4][4];
#pragma unroll
    for (int nf = 0; nf < 4; nf++)
#pragma unroll
        for (int v = 0; v < 4; v++) o[nf][v] = 0.f;
#pragma unroll
    for (int kf = 0; kf < 7; kf++) {
        unsigned a[4];
        int base = (w * 16 + g) * 60 + kf * 8 + t;
        a[0] = Ps[base]; a[1] = Ps[base + 8 * 60];
        a[2] = Ps[base + 4]; a[3] = Ps[base + 8 * 60 + 4];
#pragma unroll
        for (int nf = 0; nf < 4; nf++) {
            unsigned b[2];
            int bb = (nf * 8 + g) * 60 + kf * 8 + t;
            b[0] = Vt[bb]; b[1] = Vt[bb + 4];
            mma_tf32(o[nf], a, b);
        }
    }
#pragma unroll
    for (int nf = 0; nf < 4; nf++) {
        int col = nf * 8 + 2 * t;
        if (row0 < 49)
            *(float2*)&g_oattn[((size_t)(bn * 49) + row0) * 256 + h * 32 + col] =
                make_float2(o[nf][0], o[nf][1]);
        if (row1 < 49)
            *(float2*)&g_oattn[((size_t)(bn * 49) + row1) * 256 + h * 32 + col] =
                make_float2(o[nf][2], o[nf][3]);
    }
}

// ---------------- kernel 5: output GEMM (tf32) + bias ----------------
__global__ __launch_bounds__(256) void gemm_out_tc(const float* __restrict__ wout,
                                                   const float* __restrict__ bout) {
    __shared__ unsigned As[128 * 20];
    __shared__ unsigned Bs[64 * 20];
    int m0 = blockIdx.y * 128;
    int n0 = blockIdx.x * 64;
    int tid = threadIdx.x;
    int lane = tid & 31, wid = tid >> 5;
    int g = lane >> 2, t = lane & 3;
    int wm = (wid & 3) * 32, wn = (wid >> 2) * 32;

    float acc[2][4][4];
#pragma unroll
    for (int mf = 0; mf < 2; mf++)
#pragma unroll
        for (int nf = 0; nf < 4; nf++)
#pragma unroll
            for (int v = 0; v < 4; v++) acc[mf][nf][v] = 0.f;

    int arow = tid >> 2, ac4 = (tid & 3) * 4;
    int bkk = tid >> 4, bnn = (tid & 15) * 4;
    const float* Ab = g_oattn + (size_t)m0 * 256;

    float4 ra0 = *(const float4*)(Ab + (size_t)arow * 256 + ac4);
    float4 ra1 = *(const float4*)(Ab + (size_t)(arow + 64) * 256 + ac4);
    float4 rb  = *(const float4*)(wout + (size_t)bkk * 256 + n0 + bnn);

    for (int kt = 0; kt < 16; kt++) {
        unsigned* ap = &As[arow * 20 + ac4];
        ap[0] = f2tf(ra0.x); ap[1] = f2tf(ra0.y); ap[2] = f2tf(ra0.z); ap[3] = f2tf(ra0.w);
        ap = &As[(arow + 64) * 20 + ac4];
        ap[0] = f2tf(ra1.x); ap[1] = f2tf(ra1.y); ap[2] = f2tf(ra1.z); ap[3] = f2tf(ra1.w);
        Bs[(bnn + 0) * 20 + bkk] = f2tf(rb.x);
        Bs[(bnn + 1) * 20 + bkk] = f2tf(rb.y);
        Bs[(bnn + 2) * 20 + bkk] = f2tf(rb.z);
        Bs[(bnn + 3) * 20 + bkk] = f2tf(rb.w);
        __syncthreads();
        if (kt < 15) {
            int k0 = (kt + 1) * 16;
            ra0 = *(const float4*)(Ab + (size_t)arow * 256 + k0 + ac4);
            ra1 = *(const float4*)(Ab + (size_t)(arow + 64) * 256 + k0 + ac4);
            rb  = *(const float4*)(wout + (size_t)(k0 + bkk) * 256 + n0 + bnn);
        }
#pragma unroll
        for (int kf = 0; kf < 2; kf++) {
            unsigned a[2][4], b[4][2];
#pragma unroll
            for (int mf = 0; mf < 2; mf++) {
                int base = (wm + mf * 16 + g) * 20 + kf * 8 + t;
                a[mf][0] = As[base];
                a[mf][1] = As[base + 8 * 20];
                a[mf][2] = As[base + 4];
                a[mf][3] = As[base + 8 * 20 + 4];
            }
#pragma unroll
            for (int nf = 0; nf < 4; nf++) {
                int bb = (wn + nf * 8 + g) * 20 + kf * 8 + t;
                b[nf][0] = Bs[bb];
                b[nf][1] = Bs[bb + 4];
            }
#pragma unroll
            for (int mf = 0; mf < 2; mf++)
#pragma unroll
                for (int nf = 0; nf < 4; nf++)
                    mma_tf32(acc[mf][nf], a[mf], b[nf]);
        }
        __syncthreads();
    }

#pragma unroll
    for (int mf = 0; mf < 2; mf++) {
        int row0 = m0 + wm + mf * 16 + g;
#pragma unroll
        for (int nf = 0; nf < 4; nf++) {
            int ncol = n0 + wn + nf * 8 + 2 * t;
            float2 bv = *(const float2*)&bout[ncol];
            *(float2*)&g_otok[(size_t)row0 * 256 + ncol] =
                make_float2(acc[mf][nf][0] + bv.x, acc[mf][nf][1] + bv.y);
            *(float2*)&g_otok[(size_t)(row0 + 8) * 256 + ncol] =
                make_float2(acc[mf][nf][2] + bv.x, acc[mf][nf][3] + bv.y);
        }
    }
}

// ---------------- kernel 6: scatter ----------------
__global__ void scatter_kernel(float* __restrict__ out) {
    __shared__ float s[32 * 57];
    int xsrow = blockIdx.x;
    int c0 = blockIdx.y * 32;
    int b = blockIdx.z;
    int wi = xsrow / 7, pi = xsrow - wi * 7;
    for (int j = threadIdx.x; j < 32 * 56; j += blockDim.x) {
        int cw = j & 31, pos = j >> 5;
        int wj = pos / 7, pj = pos - wj * 7;
        int col = pos + 3; if (col >= 56) col -= 56;
        int token = (b * 64 + wi * 8 + wj) * 49 + pi * 7 + pj;
        s[cw * 57 + col] = g_otok[(size_t)token * 256 + c0 + cw];
    }
    __syncthreads();
    int r = xsrow + 3; if (r >= 56) r -= 56;
    float* ob = out + ((size_t)(b * 256 + c0) * 3136) + r * 56;
    for (int i = threadIdx.x; i < 32 * 56; i += blockDim.x) {
        int c = i / 56, col = i - c * 56;
        ob[(size_t)c * 3136 + col] = s[c * 57 + col];
    }
}

// ---------------- launch ----------------
extern "C" void kernel_launch(void* const* d_in, const int* in_sizes, int n_in,
                              void* d_out, int out_size) {
    const float* x    = (const float*)d_in[0];
    const float* pe   = (const float*)d_in[1];
    const float* wqkv = (const float*)d_in[2];
    const float* wout = (const float*)d_in[3];
    const float* bout = (const float*)d_in[4];
    float* out = (float*)d_out;

    gather_kernel<<<dim3(56, 8, 32), 256>>>(x);
    mask_kernel<<<64, 256>>>(pe);
    gemm_qkv_tc<<<dim3(12, 784), 256>>>(wqkv);
    attn_tc<<<BNW * 8, 128>>>(out);
    gemm_out_tc<<<dim3(4, 784), 256>>>(wout, bout);
    scatter_kernel<<<dim3(56, 8, 32), 256>>>(out);
}